// round 1
// baseline (speedup 1.0000x reference)
#include <cuda_runtime.h>
#include <cstdint>

// Problem constants
#define T_DIM 2048
#define B_DIM 4
#define C_DIM 1024
#define H_DIM 16
#define K_TAPS 15
#define M_DIM (T_DIM * B_DIM)     // 8192 rows (t*B + b)
#define N_DIM (H_DIM * K_TAPS)    // 240 logits per row
#define KD    C_DIM               // 1024 reduction dim

// Scratch: softmaxed dynamic weights, (T*B, 240) fp32
__device__ float g_w[M_DIM * N_DIM];

// ---------------- GEMM (tf32 mma) + fused softmax ----------------
// C[8192,240] = X[8192,1024] @ Wlin[240,1024]^T, then softmax over each
// group of 15 (per head), results to g_w.
#define BM  64
#define BK  32
#define AST 36    // padded row stride (words) for A smem: conflict-free frag loads
#define BST 36
#define CST 242   // padded stride for C staging

#define GEMM_SMEM_BYTES (BM * CST * 4)   // 61952 B (Cs is the larger union member)

__device__ __forceinline__ uint32_t f2tf(float f) {
    uint32_t u;
    asm("cvt.rna.tf32.f32 %0, %1;" : "=r"(u) : "f"(f));
    return u;
}

extern "C" __global__ void __launch_bounds__(256, 1)
gemm_softmax_kernel(const float* __restrict__ x, const float* __restrict__ Wlin) {
    extern __shared__ uint32_t sm[];
    uint32_t* As = sm;                       // [BM][AST] tf32
    uint32_t* Bs = sm + BM * AST;            // [N_DIM][BST] tf32
    float*    Cs = (float*)sm;               // [BM][CST] (reused after mainloop)

    const int tid  = threadIdx.x;
    const int wid  = tid >> 5;
    const int lane = tid & 31;
    const int m0   = blockIdx.x * BM;

    const int wm    = wid & 3;        // 4 M-warps
    const int wn    = wid >> 2;       // 2 N-warps
    const int mbase = wm * 16;
    const int nbase = wn * 120;
    const int lg    = lane >> 2;      // group id 0..7
    const int lk    = lane & 3;       // thread-in-group 0..3

    float acc[15][4];
    #pragma unroll
    for (int i = 0; i < 15; i++)
        #pragma unroll
        for (int j = 0; j < 4; j++) acc[i][j] = 0.f;

    for (int kb = 0; kb < KD; kb += BK) {
        __syncthreads();
        // Load A tile: 64 rows x 32 k = 512 float4
        #pragma unroll
        for (int it = 0; it < 2; it++) {
            int idx = it * 256 + tid;
            int m = idx >> 3, kq = idx & 7;
            const float4 v = *(const float4*)(x + (size_t)(m0 + m) * KD + kb + kq * 4);
            uint32_t* d = As + m * AST + kq * 4;
            d[0] = f2tf(v.x); d[1] = f2tf(v.y); d[2] = f2tf(v.z); d[3] = f2tf(v.w);
        }
        // Load B tile: 240 rows x 32 k = 1920 float4
        #pragma unroll
        for (int it = 0; it < 8; it++) {
            int idx = it * 256 + tid;
            if (idx < 1920) {
                int n = idx >> 3, kq = idx & 7;
                const float4 v = *(const float4*)(Wlin + (size_t)n * KD + kb + kq * 4);
                uint32_t* d = Bs + n * BST + kq * 4;
                d[0] = f2tf(v.x); d[1] = f2tf(v.y); d[2] = f2tf(v.z); d[3] = f2tf(v.w);
            }
        }
        __syncthreads();

        #pragma unroll
        for (int kk = 0; kk < BK; kk += 8) {
            uint32_t a0 = As[(mbase     + lg) * AST + kk     + lk];
            uint32_t a1 = As[(mbase + 8 + lg) * AST + kk     + lk];
            uint32_t a2 = As[(mbase     + lg) * AST + kk + 4 + lk];
            uint32_t a3 = As[(mbase + 8 + lg) * AST + kk + 4 + lk];
            #pragma unroll
            for (int nt = 0; nt < 15; nt++) {
                uint32_t b0 = Bs[(nbase + nt * 8 + lg) * BST + kk     + lk];
                uint32_t b1 = Bs[(nbase + nt * 8 + lg) * BST + kk + 4 + lk];
                asm volatile(
                    "mma.sync.aligned.m16n8k8.row.col.f32.tf32.tf32.f32 "
                    "{%0,%1,%2,%3}, {%4,%5,%6,%7}, {%8,%9}, {%0,%1,%2,%3};\n"
                    : "+f"(acc[nt][0]), "+f"(acc[nt][1]),
                      "+f"(acc[nt][2]), "+f"(acc[nt][3])
                    : "r"(a0), "r"(a1), "r"(a2), "r"(a3), "r"(b0), "r"(b1));
            }
        }
    }

    __syncthreads();   // everyone done with As/Bs before Cs overwrite

    // Stage C tile in smem. m16n8 f32 frag layout:
    // c0:(lg, 2*lk) c1:(lg, 2*lk+1) c2:(lg+8, 2*lk) c3:(lg+8, 2*lk+1)
    #pragma unroll
    for (int nt = 0; nt < 15; nt++) {
        int col = nbase + nt * 8 + 2 * lk;
        Cs[(mbase     + lg) * CST + col    ] = acc[nt][0];
        Cs[(mbase     + lg) * CST + col + 1] = acc[nt][1];
        Cs[(mbase + 8 + lg) * CST + col    ] = acc[nt][2];
        Cs[(mbase + 8 + lg) * CST + col + 1] = acc[nt][3];
    }
    __syncthreads();

    // Softmax over K=15 per (row, head): 64*16 = 1024 tasks
    #pragma unroll
    for (int it = 0; it < 4; it++) {
        int task = it * 256 + tid;
        int row = task >> 4, h = task & 15;
        const float* p = Cs + row * CST + h * K_TAPS;
        float mx = p[0];
        #pragma unroll
        for (int k = 1; k < K_TAPS; k++) mx = fmaxf(mx, p[k]);
        float e[K_TAPS];
        float s = 0.f;
        #pragma unroll
        for (int k = 0; k < K_TAPS; k++) { e[k] = __expf(p[k] - mx); s += e[k]; }
        float r = 1.0f / s;
        float* o = g_w + (size_t)(m0 + row) * N_DIM + h * K_TAPS;
        #pragma unroll
        for (int k = 0; k < K_TAPS; k++) o[k] = e[k] * r;
    }
}

// ---------------- Dynamic depthwise conv (causal, K=15) ----------------
// out[t,b,c] = sum_k w[t,b,h(c),k] * x[t+k-14, b, c]
// Rolling register window of 15 float4 per thread; each x row read once.
#define TT 32   // time steps per block

extern "C" __global__ void __launch_bounds__(256, 2)
dynconv_kernel(const float* __restrict__ x, float* __restrict__ out) {
    __shared__ float ws[TT * N_DIM];   // weights for this time tile: 30 KB

    const int tid = threadIdx.x;
    const int t0  = blockIdx.x * TT;
    const int b   = blockIdx.y;

    // Load softmaxed weights for rows (t0..t0+TT-1, b): TT*240 = 7680 floats
    const float4* gw4 = (const float4*)g_w;
    #pragma unroll
    for (int it = 0; it < 8; it++) {
        int idx = it * 256 + tid;            // 0..1919 float4
        if (idx < TT * (N_DIM / 4)) {
            int tt = idx / (N_DIM / 4), q = idx % (N_DIM / 4);
            ((float4*)ws)[tt * (N_DIM / 4) + q] =
                gw4[(size_t)((t0 + tt) * B_DIM + b) * (N_DIM / 4) + q];
        }
    }
    __syncthreads();

    const int c4 = tid;           // float4 channel group (c = 4*tid)
    const int h  = tid >> 4;      // head = (4*tid)/64

    const float4* x4 = (const float4*)x;
    float4*       o4 = (float4*)out;

    // Initial window: rows t0-14 .. t0 (zero below 0)
    float4 win[K_TAPS];
    #pragma unroll
    for (int i = 0; i < K_TAPS; i++) {
        int t = t0 - 14 + i;
        win[i] = (t < 0) ? make_float4(0.f, 0.f, 0.f, 0.f)
                         : x4[(size_t)(t * B_DIM + b) * (C_DIM / 4) + c4];
    }

    #pragma unroll
    for (int tt = 0; tt < TT; tt++) {
        const float* wr = ws + tt * N_DIM + h * K_TAPS;
        float4 a = make_float4(0.f, 0.f, 0.f, 0.f);
        #pragma unroll
        for (int k = 0; k < K_TAPS; k++) {
            const float w = wr[k];
            const float4 xv = win[(tt + k) % K_TAPS];
            a.x += w * xv.x; a.y += w * xv.y;
            a.z += w * xv.z; a.w += w * xv.w;
        }
        o4[(size_t)((t0 + tt) * B_DIM + b) * (C_DIM / 4) + c4] = a;
        if (tt + 1 < TT) {
            int t = t0 + tt + 1;   // slide: replace oldest row (t0+tt-14)
            win[tt % K_TAPS] = x4[(size_t)(t * B_DIM + b) * (C_DIM / 4) + c4];
        }
    }
}

extern "C" void kernel_launch(void* const* d_in, const int* in_sizes, int n_in,
                              void* d_out, int out_size) {
    const float* x    = (const float*)d_in[0];   // (T, B, C) f32
    const float* Wlin = (const float*)d_in[1];   // (240, 1024) f32
    float* out = (float*)d_out;                  // (T, B, C) f32

    cudaFuncSetAttribute(gemm_softmax_kernel,
                         cudaFuncAttributeMaxDynamicSharedMemorySize,
                         GEMM_SMEM_BYTES);

    gemm_softmax_kernel<<<M_DIM / BM, 256, GEMM_SMEM_BYTES>>>(x, Wlin);
    dynconv_kernel<<<dim3(T_DIM / TT, B_DIM), 256>>>(x, out);
}

// round 2
// speedup vs baseline: 1.1859x; 1.1859x over previous
#include <cuda_runtime.h>
#include <cstdint>

// Problem constants
#define T_DIM 2048
#define B_DIM 4
#define C_DIM 1024
#define H_DIM 16
#define K_TAPS 15
#define M_DIM (T_DIM * B_DIM)     // 8192 rows (t*B + b)
#define N_DIM (H_DIM * K_TAPS)    // 240 logits per row
#define KD    C_DIM               // 1024 reduction dim

// Scratch: softmaxed dynamic weights (T*B, 240) fp32; pre-rounded tf32 Wlin
__device__ float    g_w[M_DIM * N_DIM];
__device__ uint32_t g_bw[N_DIM * KD];

__device__ __forceinline__ uint32_t f2tf(float f) {
    uint32_t u;
    asm("cvt.rna.tf32.f32 %0, %1;" : "=r"(u) : "f"(f));
    return u;
}

// ---------------- Prologue: Wlin -> tf32(rna) bits, once ----------------
extern "C" __global__ void __launch_bounds__(256)
cvt_b_kernel(const float* __restrict__ W) {
    int i = blockIdx.x * 256 + threadIdx.x;      // 61440 float4 total
    float4 v = ((const float4*)W)[i];
    uint4 o;
    o.x = f2tf(v.x); o.y = f2tf(v.y); o.z = f2tf(v.z); o.w = f2tf(v.w);
    ((uint4*)g_bw)[i] = o;
}

// ---------------- GEMM (tf32 mma, cp.async 3-stage) + fused softmax -----
#define BM   64
#define BK   32
#define NT   (KD / BK)            // 32 k-tiles
#define AST  36                   // padded stride (words), 144B rows (16B aligned)
#define BST  36
#define A_STAGE (BM * AST)        // 2304 words
#define B_STAGE (N_DIM * BST)     // 8640 words
#define STAGE_W (A_STAGE + B_STAGE)
#define NSTAGE  3
#define GEMM_SMEM_BYTES (NSTAGE * STAGE_W * 4)   // 131328 B
#define CST 242

extern "C" __global__ void __launch_bounds__(256, 1)
gemm_softmax_kernel(const float* __restrict__ x) {
    extern __shared__ uint32_t sm[];
    const int tid  = threadIdx.x;
    const int wid  = tid >> 5;
    const int lane = tid & 31;
    const int m0   = blockIdx.x * BM;

    const int wm    = wid & 3;        // 4 M-warps
    const int wn    = wid >> 2;       // 2 N-warps
    const int mbase = wm * 16;
    const int nbase = wn * 120;
    const int lg    = lane >> 2;
    const int lk    = lane & 3;

    auto issue_tile = [&](int kb, int s) {
        uint32_t* As = sm + s * STAGE_W;
        uint32_t* Bs = As + A_STAGE;
        // A tile: 64 x 32 = 512 float4 (raw f32 bits; HW truncates to tf32)
        #pragma unroll
        for (int it = 0; it < 2; it++) {
            int idx = it * 256 + tid;
            int m = idx >> 3, kq = idx & 7;
            const float* src = x + (size_t)(m0 + m) * KD + kb + kq * 4;
            uint32_t dst = (uint32_t)__cvta_generic_to_shared(As + m * AST + kq * 4);
            asm volatile("cp.async.cg.shared.global [%0], [%1], 16;\n"
                         :: "r"(dst), "l"(src));
        }
        // B tile: 240 x 32 = 1920 float4 (pre-rounded tf32)
        #pragma unroll
        for (int it = 0; it < 8; it++) {
            int idx = it * 256 + tid;
            if (idx < 1920) {
                int n = idx >> 3, kq = idx & 7;
                const uint32_t* src = g_bw + (size_t)n * KD + kb + kq * 4;
                uint32_t dst = (uint32_t)__cvta_generic_to_shared(Bs + n * BST + kq * 4);
                asm volatile("cp.async.cg.shared.global [%0], [%1], 16;\n"
                             :: "r"(dst), "l"(src));
            }
        }
        asm volatile("cp.async.commit_group;\n");
    };

    float acc[15][4];
    #pragma unroll
    for (int i = 0; i < 15; i++)
        #pragma unroll
        for (int j = 0; j < 4; j++) acc[i][j] = 0.f;

    // Prologue: prefetch 2 tiles
    issue_tile(0, 0);
    issue_tile(BK, 1);

    for (int kbi = 0; kbi < NT; kbi++) {
        const int s_cur = kbi % NSTAGE;
        if (kbi + 2 < NT) issue_tile((kbi + 2) * BK, (kbi + 2) % NSTAGE);

        // Wait for tile kbi's group (per-thread), then make it block-visible
        if (kbi < NT - 2)       asm volatile("cp.async.wait_group %0;\n" :: "n"(2));
        else if (kbi == NT - 2) asm volatile("cp.async.wait_group %0;\n" :: "n"(1));
        else                    asm volatile("cp.async.wait_group %0;\n" :: "n"(0));
        __syncthreads();

        const uint32_t* As = sm + s_cur * STAGE_W;
        const uint32_t* Bs = As + A_STAGE;

        #pragma unroll
        for (int kk = 0; kk < BK; kk += 8) {
            uint32_t a0 = As[(mbase     + lg) * AST + kk     + lk];
            uint32_t a1 = As[(mbase + 8 + lg) * AST + kk     + lk];
            uint32_t a2 = As[(mbase     + lg) * AST + kk + 4 + lk];
            uint32_t a3 = As[(mbase + 8 + lg) * AST + kk + 4 + lk];
            #pragma unroll
            for (int nt = 0; nt < 15; nt++) {
                uint32_t b0 = Bs[(nbase + nt * 8 + lg) * BST + kk     + lk];
                uint32_t b1 = Bs[(nbase + nt * 8 + lg) * BST + kk + 4 + lk];
                asm volatile(
                    "mma.sync.aligned.m16n8k8.row.col.f32.tf32.tf32.f32 "
                    "{%0,%1,%2,%3}, {%4,%5,%6,%7}, {%8,%9}, {%0,%1,%2,%3};\n"
                    : "+f"(acc[nt][0]), "+f"(acc[nt][1]),
                      "+f"(acc[nt][2]), "+f"(acc[nt][3])
                    : "r"(a0), "r"(a1), "r"(a2), "r"(a3), "r"(b0), "r"(b1));
            }
        }
        __syncthreads();   // stage s_cur is overwritten by issue at kbi+1
    }

    // ---- Epilogue: stage C in smem, softmax over K=15 per head ----
    float* Cs = (float*)sm;   // 64 x 242 floats, reuses stage buffers
    #pragma unroll
    for (int nt = 0; nt < 15; nt++) {
        int col = nbase + nt * 8 + 2 * lk;
        Cs[(mbase     + lg) * CST + col    ] = acc[nt][0];
        Cs[(mbase     + lg) * CST + col + 1] = acc[nt][1];
        Cs[(mbase + 8 + lg) * CST + col    ] = acc[nt][2];
        Cs[(mbase + 8 + lg) * CST + col + 1] = acc[nt][3];
    }
    __syncthreads();

    #pragma unroll
    for (int it = 0; it < 4; it++) {
        int task = it * 256 + tid;          // 64 rows x 16 heads
        int row = task >> 4, h = task & 15;
        const float* p = Cs + row * CST + h * K_TAPS;
        float mx = p[0];
        #pragma unroll
        for (int k = 1; k < K_TAPS; k++) mx = fmaxf(mx, p[k]);
        float e[K_TAPS];
        float s = 0.f;
        #pragma unroll
        for (int k = 0; k < K_TAPS; k++) { e[k] = __expf(p[k] - mx); s += e[k]; }
        float r = 1.0f / s;
        float* o = g_w + (size_t)(m0 + row) * N_DIM + h * K_TAPS;
        #pragma unroll
        for (int k = 0; k < K_TAPS; k++) o[k] = e[k] * r;
    }
}

// ---------------- Dynamic depthwise conv (causal, K=15) ----------------
// out[t,b,c] = sum_k w[t,b,h(c),k] * x[t+k-14, b, c]
#define TT 32   // time steps per block

extern "C" __global__ void __launch_bounds__(256, 2)
dynconv_kernel(const float* __restrict__ x, float* __restrict__ out) {
    __shared__ float ws[TT * N_DIM];   // weights for this time tile: 30 KB

    const int tid = threadIdx.x;
    const int t0  = blockIdx.x * TT;
    const int b   = blockIdx.y;

    const int c4 = tid;           // float4 channel group (c = 4*tid)
    const int h  = tid >> 4;      // head = (4*tid)/64

    const float4* x4 = (const float4*)x;
    float4*       o4 = (float4*)out;

    // Kick off the register window loads first (15 independent LDGs in flight)
    float4 win[K_TAPS];
    #pragma unroll
    for (int i = 0; i < K_TAPS; i++) {
        int t = t0 - 14 + i;
        win[i] = (t < 0) ? make_float4(0.f, 0.f, 0.f, 0.f)
                         : x4[(size_t)(t * B_DIM + b) * (C_DIM / 4) + c4];
    }

    // Then fill the weight tile (overlaps with window loads)
    const float4* gw4 = (const float4*)g_w;
    #pragma unroll
    for (int it = 0; it < 8; it++) {
        int idx = it * 256 + tid;            // 0..1919 float4
        if (idx < TT * (N_DIM / 4)) {
            int tt = idx / (N_DIM / 4), q = idx % (N_DIM / 4);
            ((float4*)ws)[tt * (N_DIM / 4) + q] =
                gw4[(size_t)((t0 + tt) * B_DIM + b) * (N_DIM / 4) + q];
        }
    }
    __syncthreads();

    #pragma unroll
    for (int tt = 0; tt < TT; tt++) {
        // Prefetch next x row BEFORE the reduction to hide LDG latency
        float4 nxt;
        if (tt + 1 < TT)
            nxt = x4[(size_t)((t0 + tt + 1) * B_DIM + b) * (C_DIM / 4) + c4];

        const float* wr = ws + tt * N_DIM + h * K_TAPS;
        float4 a = make_float4(0.f, 0.f, 0.f, 0.f);
        #pragma unroll
        for (int k = 0; k < K_TAPS; k++) {
            const float w = wr[k];
            const float4 xv = win[(tt + k) % K_TAPS];
            a.x += w * xv.x; a.y += w * xv.y;
            a.z += w * xv.z; a.w += w * xv.w;
        }
        o4[(size_t)((t0 + tt) * B_DIM + b) * (C_DIM / 4) + c4] = a;
        if (tt + 1 < TT) win[tt % K_TAPS] = nxt;
    }
}

extern "C" void kernel_launch(void* const* d_in, const int* in_sizes, int n_in,
                              void* d_out, int out_size) {
    const float* x    = (const float*)d_in[0];   // (T, B, C) f32
    const float* Wlin = (const float*)d_in[1];   // (240, 1024) f32
    float* out = (float*)d_out;                  // (T, B, C) f32

    cudaFuncSetAttribute(gemm_softmax_kernel,
                         cudaFuncAttributeMaxDynamicSharedMemorySize,
                         GEMM_SMEM_BYTES);

    cvt_b_kernel<<<N_DIM, 256>>>(Wlin);                      // 61440 float4
    gemm_softmax_kernel<<<M_DIM / BM, 256, GEMM_SMEM_BYTES>>>(x);
    dynconv_kernel<<<dim3(T_DIM / TT, B_DIM), 256>>>(x, out);
}